// round 4
// baseline (speedup 1.0000x reference)
#include <cuda_runtime.h>
#include <cooperative_groups.h>
namespace cg = cooperative_groups;

// ---------------- problem constants (fixed by setup_inputs) ----------------
#define G        64      // gt boxes per batch
#define A        5       // anchors per location
#define S        25      // score map size
#define NANCH    3125    // S*S*A
#define BMAX     128     // batch
#define POS_NUM  16
#define TOTAL_NUM 64
#define THR_HIGH 0.6f
#define THR_LOW  0.3f

#define CPB      7       // CTAs per batch image (cluster size, 7*447 >= 3125)
#define NPC      447     // anchors per CTA
#define BLK      512     // threads per CTA

__device__ signed char g_cls[BMAX * NANCH];

// IEEE round-to-nearest IoU, explicit _rn ops (non-contractible -> identical
// bits for identical inputs everywhere; required for the == keep semantics).
__device__ __forceinline__ float iou_rn(float ax1, float ay1, float ax2, float ay2,
                                        float area_a,
                                        float gx1, float gy1, float gx2, float gy2,
                                        float area_g) {
    float ix = __fadd_rn(__fsub_rn(fminf(ax2, gx2), fmaxf(ax1, gx1)), 1.0f);
    float iy = __fadd_rn(__fsub_rn(fminf(ay2, gy2), fmaxf(ay1, gy1)), 1.0f);
    float inter = __fmul_rn(fmaxf(ix, 0.0f), fmaxf(iy, 0.0f));
    float denom = __fsub_rn(__fadd_rn(area_a, area_g), inter);
    return __fdiv_rn(inter, denom);
}

// ---------------- K1: single-pass IoU + cluster-wide gt_max + everything ---
// grid (CPB, B), block 512, cluster (CPB,1,1): one cluster per batch image.
__global__ void __cluster_dims__(CPB, 1, 1)
k_main(const float4* __restrict__ anchors,
       const float4* __restrict__ gt,
       float* __restrict__ out, int Bn) {
    extern __shared__ float sv[];            // [G][BLK] iou tile (128 KB)
    __shared__ float4   s_gtv[G];
    __shared__ float    s_gar[G];
    __shared__ unsigned s_part[G];           // this CTA's per-gt partial max (bits)
    __shared__ unsigned s_gtm[G];            // cluster-wide per-gt max (bits)

    cg::cluster_group cl = cg::this_cluster();
    const int r  = blockIdx.x;               // rank in cluster
    const int bA = blockIdx.y;
    const int t  = threadIdx.x;

    if (t < G) {
        float4 q = gt[bA * G + t];
        s_gtv[t] = q;
        float gw = __fadd_rn(__fsub_rn(q.z, q.x), 1.0f);
        float gh = __fadd_rn(__fsub_rn(q.w, q.y), 1.0f);
        s_gar[t] = __fmul_rn(gw, gh);
        s_part[t] = 0u;
    }
    __syncthreads();

    const int  n     = r * NPC + t;
    const bool valid = (t < NPC) && (n < NANCH);
    float4 a4 = anchors[valid ? n : 0];
    float aw = __fadd_rn(__fsub_rn(a4.z, a4.x), 1.0f);
    float ah = __fadd_rn(__fsub_rn(a4.w, a4.y), 1.0f);
    float area_a = __fmul_rn(aw, ah);

    float maxv = -1.0f;
    int   arg  = 0;
#pragma unroll 4
    for (int g = 0; g < G; g++) {
        float4 q = s_gtv[g];
        float v = iou_rn(a4.x, a4.y, a4.z, a4.w, area_a,
                         q.x, q.y, q.z, q.w, s_gar[g]);
        sv[g * BLK + t] = v;                           // conflict-free STS
        if (v > maxv) { maxv = v; arg = g; }           // strict >: first argmax
        unsigned u = valid ? __float_as_uint(v) : 0u;  // v>=0 -> bits monotonic
        unsigned m = __reduce_max_sync(0xffffffffu, u);
        if ((t & 31) == 0 && m) atomicMax(&s_part[g], m);
    }
    __syncthreads();
    cl.sync();                                         // partials visible cluster-wide

    if (t < G) {
        unsigned m = 0u;
        for (int rr = 0; rr < CPB; rr++) {
            const unsigned* p = cl.map_shared_rank((const unsigned*)s_part, rr);
            unsigned x = p[t];
            if (x > m) m = x;
        }
        s_gtm[t] = m;
    }
    __syncthreads();

    if (valid) {
        bool keep = false;
#pragma unroll 8
        for (int g = 0; g < G; g++) {
            unsigned gm = s_gtm[g];
            keep |= (gm != 0u) && (__float_as_uint(sv[g * BLK + t]) == gm);
        }
        int cls = -1;
        if (maxv >= THR_HIGH) cls = 1;
        if (maxv <= THR_LOW)  cls = 0;
        if (keep)             cls = 1;
        const long idx = (long)bA * NANCH + n;
        g_cls[idx] = (signed char)cls;

        out[(long)Bn * NANCH * 6 + idx] = maxv;        // max_ov (region 6)

        // bt deltas (regions 1..4), transposed to (b, 4, A, S, S)
        float4 q = s_gtv[arg];
        float acx = a4.x + 0.5f * aw, acy = a4.y + 0.5f * ah;
        float gw = q.z - q.x + 1.0f,  gh = q.w - q.y + 1.0f;
        float gcx = q.x + 0.5f * gw,  gcy = q.y + 0.5f * gh;
        float dx = __fdividef(gcx - acx, aw);
        float dy = __fdividef(gcy - acy, ah);
        float dw = __logf(__fdividef(gw, aw));
        float dh = __logf(__fdividef(gh, ah));

        const int a = n % A, yx = n / A;
        long o = (long)Bn * NANCH + ((long)(bA * 4) * A + a) * (S * S) + yx;
        out[o]             = dx;
        out[o + NANCH]     = dy;
        out[o + 2 * NANCH] = dw;
        out[o + 3 * NANCH] = dh;
    }
    cl.sync();   // peers must not exit while our DSMEM reads may be in flight
}

// ---------------- K2: per-batch pos/neg cumsum truncation, cls/bw writes ---
// 1024 threads/block, chunk=4, two-level scan. pos_num of LAST batch computed
// locally (no global counter / init kernel needed).
__global__ void k_scan(float* __restrict__ out, int Bn) {
    __shared__ int wsum[32];
    __shared__ int s_pos;
    const int bA = blockIdx.x;
    const int t  = threadIdx.x;                      // 1024 threads
    const int lane = t & 31, wid = t >> 5;

    if (t == 0) s_pos = 0;
    __syncthreads();

    // pos count of last batch (after-truncation count == min(raw,POS_NUM))
    int lp = 0;
    for (int n = t; n < NANCH; n += 1024)
        lp += (g_cls[(long)(Bn - 1) * NANCH + n] == 1);
#pragma unroll
    for (int off = 16; off; off >>= 1) lp += __shfl_down_sync(0xffffffffu, lp, off);
    if (lane == 0 && lp) atomicAdd(&s_pos, lp);

    const int CH = 4;                                // ceil(3125/1024)
    const int start = t * CH;
    const int end   = min(start + CH, NANCH);

    int pc = 0, nc = 0;
    for (int n = start; n < end; n++) {
        int c = g_cls[(long)bA * NANCH + n];
        pc += (c == 1);
        nc += (c == 0);
    }
    int v = (pc << 16) | nc;
    int inc = v;
#pragma unroll
    for (int off = 1; off < 32; off <<= 1) {
        int u = __shfl_up_sync(0xffffffffu, inc, off);
        if (lane >= off) inc += u;
    }
    if (lane == 31) wsum[wid] = inc;
    __syncthreads();
    if (wid == 0) {
        int w = wsum[lane];
        int wi = w;
#pragma unroll
        for (int off = 1; off < 32; off <<= 1) {
            int u = __shfl_up_sync(0xffffffffu, wi, off);
            if (lane >= off) wi += u;
        }
        wsum[lane] = wi - w;                         // exclusive warp offsets
    }
    __syncthreads();
    int exc = (inc - v) + wsum[wid];
    int prun = exc >> 16;
    int nrun = exc & 0xffff;

    const int pn = min(s_pos, POS_NUM);
    const float invp = 1.0f / (float)pn;             // pn==0 -> inf, matches ref
    const long bwOff = (long)Bn * NANCH * 5;         // cls(1) + bt(4)

    for (int n = start; n < end; n++) {
        int c = g_cls[(long)bA * NANCH + n];
        if (c == 1)      { prun++; if (prun > POS_NUM)   c = -1; }
        else if (c == 0) { nrun++; if (nrun > TOTAL_NUM) c = -1; }
        float bw = (c == 1) ? invp : 0.0f;
        int a = n % A, yx = n / A;
        long ci = ((long)bA * A + a) * (S * S) + yx;
        out[ci]         = (float)c;
        out[bwOff + ci] = bw;
    }
}

// ---------------- launch ----------------------------------------------------
extern "C" void kernel_launch(void* const* d_in, const int* in_sizes, int n_in,
                              void* d_out, int out_size) {
    (void)n_in; (void)out_size;
    const float4* gt      = (const float4*)d_in[0];   // (B, G, 4)
    const float4* anchors = (const float4*)d_in[1];   // (N, 4)
    const int Bn = in_sizes[0] / (G * 4);             // 128
    float* out = (float*)d_out;

    const int smem = G * BLK * sizeof(float);         // 128 KB iou tile
    cudaFuncSetAttribute(k_main, cudaFuncAttributeMaxDynamicSharedMemorySize, smem);

    dim3 g1(CPB, Bn);
    k_main<<<g1, BLK, smem>>>(anchors, gt, out, Bn);
    k_scan<<<Bn, 1024>>>(out, Bn);
}

// round 5
// speedup vs baseline: 2.2117x; 2.2117x over previous
#include <cuda_runtime.h>

// ---------------- problem constants (fixed by setup_inputs) ----------------
#define G        64      // gt boxes per batch
#define A        5       // anchors per location
#define S        25      // score map size
#define NANCH    3125    // S*S*A
#define NBLK     25      // iou blocks per batch (25*128 >= 3125)
#define BMAX     128     // batch
#define POS_NUM  16
#define TOTAL_NUM 64
#define THR_HIGH 0.6f
#define THR_LOW  0.3f

// ---------------- scratch (device globals; no allocation allowed) ----------
__device__ unsigned           g_gtmax[BMAX * G];          // per-(b,g) max iou bits
__device__ unsigned           g_bmax [BMAX * NBLK * G];   // per-(b,blk,g) block max bits
__device__ unsigned long long g_mask [BMAX * NANCH];      // per-anchor block-tie mask
__device__ signed char        g_cls  [BMAX * NANCH];

// ---------------- K0: zero the atomicMax target ----------------------------
__global__ void k_init() {
    int i = blockIdx.x * blockDim.x + threadIdx.x;
    if (i < BMAX * G) g_gtmax[i] = 0u;
}

// IEEE round-to-nearest IoU, explicit _rn ops (non-contractible). Computed
// exactly ONCE per (anchor,gt); tie detection uses the stored bits.
__device__ __forceinline__ float iou_rn(float ax1, float ay1, float ax2, float ay2,
                                        float area_a,
                                        float gx1, float gy1, float gx2, float gy2,
                                        float area_g) {
    float ix = __fadd_rn(__fsub_rn(fminf(ax2, gx2), fmaxf(ax1, gx1)), 1.0f);
    float iy = __fadd_rn(__fsub_rn(fminf(ay2, gy2), fmaxf(ay1, gy1)), 1.0f);
    float inter = __fmul_rn(fmaxf(ix, 0.0f), fmaxf(iy, 0.0f));
    float denom = __fsub_rn(__fadd_rn(area_a, area_g), inter);
    return __fdiv_rn(inter, denom);
}

// ---------------- K1: single IoU pass -> maxov, bt, blockmax, tie mask -----
// grid (NBLK, B), block 128.
__global__ void k_iou(const float4* __restrict__ anchors,
                      const float4* __restrict__ gt,
                      float* __restrict__ out, int Bn) {
    __shared__ float    sv[128 * 65];        // iou tile, 65-pad: conflict-free
    __shared__ float4   s_gtv[G];
    __shared__ float    s_gar[G];
    __shared__ unsigned s_wmax[G][4];        // per-warp per-g max bits
    __shared__ unsigned s_bmax[G];

    const int blk = blockIdx.x, bA = blockIdx.y, t = threadIdx.x;
    const int wid = t >> 5;

    if (t < G) {
        float4 q = gt[bA * G + t];
        s_gtv[t] = q;
        float gw = __fadd_rn(__fsub_rn(q.z, q.x), 1.0f);
        float gh = __fadd_rn(__fsub_rn(q.w, q.y), 1.0f);
        s_gar[t] = __fmul_rn(gw, gh);
    }
    __syncthreads();

    const int  n     = blk * 128 + t;
    const bool valid = (n < NANCH);
    float4 a4 = anchors[valid ? n : 0];
    float aw = __fadd_rn(__fsub_rn(a4.z, a4.x), 1.0f);
    float ah = __fadd_rn(__fsub_rn(a4.w, a4.y), 1.0f);
    float area_a = __fmul_rn(aw, ah);

    float maxv = -1.0f;
    int   arg  = 0;
#pragma unroll 4
    for (int g = 0; g < G; g++) {
        float4 q = s_gtv[g];
        float v = iou_rn(a4.x, a4.y, a4.z, a4.w, area_a,
                         q.x, q.y, q.z, q.w, s_gar[g]);
        sv[t * 65 + g] = v;
        if (v > maxv) { maxv = v; arg = g; }            // strict >: first argmax
        unsigned u = valid ? __float_as_uint(v) : 0u;   // v>=0 -> bits monotonic
        unsigned m = __reduce_max_sync(0xffffffffu, u);
        if ((t & 31) == 0) s_wmax[g][wid] = m;
    }

    // maxov + bt can go out now (argmax is final; overlaps reduction latency)
    if (valid) {
        const long idx = (long)bA * NANCH + n;
        out[(long)Bn * NANCH * 6 + idx] = maxv;

        float4 q = s_gtv[arg];
        float acx = a4.x + 0.5f * aw, acy = a4.y + 0.5f * ah;
        float gw = q.z - q.x + 1.0f,  gh = q.w - q.y + 1.0f;
        float gcx = q.x + 0.5f * gw,  gcy = q.y + 0.5f * gh;
        float dx = __fdividef(gcx - acx, aw);
        float dy = __fdividef(gcy - acy, ah);
        float dw = __logf(__fdividef(gw, aw));
        float dh = __logf(__fdividef(gh, ah));

        const int a = n % A, yx = n / A;
        long o = (long)Bn * NANCH + ((long)(bA * 4) * A + a) * (S * S) + yx;
        out[o]             = dx;
        out[o + NANCH]     = dy;       // +1 delta-channel = +A*S*S = NANCH
        out[o + 2 * NANCH] = dw;
        out[o + 3 * NANCH] = dh;
    }
    __syncthreads();

    if (t < G) {
        unsigned bm = max(max(s_wmax[t][0], s_wmax[t][1]),
                          max(s_wmax[t][2], s_wmax[t][3]));
        s_bmax[t] = bm;
        g_bmax[(bA * NBLK + blk) * G + t] = bm;
        if (bm) atomicMax(&g_gtmax[bA * G + t], bm);
    }
    __syncthreads();

    if (valid) {
        unsigned long long mask = 0ull;
#pragma unroll 8
        for (int g = 0; g < G; g++) {
            mask |= (unsigned long long)(__float_as_uint(sv[t * 65 + g]) == s_bmax[g]) << g;
        }
        g_mask[(long)bA * NANCH + n] = mask;
    }
}

// ---------------- K2: keep = tiemask & winner mask -> cls ------------------
// grid (NBLK, B), block 128. An anchor ties the GLOBAL gt max iff it ties its
// block max AND its block max equals the global max (gtmax >= bmax >= v).
__global__ void k_cls(const float* __restrict__ out, int Bn) {
    __shared__ unsigned s_w[2];
    const int blk = blockIdx.x, bA = blockIdx.y, t = threadIdx.x;
    const int wid = t >> 5, lane = t & 31;

    if (wid < 2) {                               // g = t in [0,64)
        unsigned bm = g_bmax[(bA * NBLK + blk) * G + t];
        unsigned gm = g_gtmax[bA * G + t];
        bool w = (gm != 0u) && (bm == gm);       // gtmax==0 -> ref's 1e-5: no match
        unsigned bal = __ballot_sync(0xffffffffu, w);
        if (lane == 0) s_w[wid] = bal;
    }
    __syncthreads();

    const int n = blk * 128 + t;
    if (n >= NANCH) return;
    const unsigned long long W = s_w[0] | ((unsigned long long)s_w[1] << 32);
    const long idx = (long)bA * NANCH + n;
    float maxv = out[(long)Bn * NANCH * 6 + idx];
    int cls = -1;
    if (maxv >= THR_HIGH) cls = 1;
    if (maxv <= THR_LOW)  cls = 0;
    if (g_mask[idx] & W)  cls = 1;
    g_cls[idx] = (signed char)cls;
}

// ---------------- K3: per-batch cumsum truncation, coalesced cls/bw --------
// block = one batch, 1024 threads. Final cls staged in smem; both output
// regions written in OUTPUT-linear order (fully coalesced).
__global__ void k_scan(float* __restrict__ out, int Bn) {
    __shared__ int wsum[32];
    __shared__ int s_pos;
    __shared__ signed char s_cls[NANCH + 3];
    const int bA = blockIdx.x, t = threadIdx.x;
    const int lane = t & 31, wid = t >> 5;

    if (t == 0) s_pos = 0;
    __syncthreads();

    // pre-truncation pos count of LAST batch (post-trunc = min(raw, POS_NUM))
    int lp = 0;
    for (int n = t; n < NANCH; n += 1024)
        lp += (g_cls[(long)(Bn - 1) * NANCH + n] == 1);
#pragma unroll
    for (int off = 16; off; off >>= 1) lp += __shfl_down_sync(0xffffffffu, lp, off);
    if (lane == 0 && lp) atomicAdd(&s_pos, lp);

    const int CH = 4;
    const int start = t * CH;
    const int end   = min(start + CH, NANCH);

    int pc = 0, nc = 0;
    for (int n = start; n < end; n++) {
        int c = g_cls[(long)bA * NANCH + n];
        pc += (c == 1);
        nc += (c == 0);
    }
    int v = (pc << 16) | nc;
    int inc = v;
#pragma unroll
    for (int off = 1; off < 32; off <<= 1) {
        int u = __shfl_up_sync(0xffffffffu, inc, off);
        if (lane >= off) inc += u;
    }
    if (lane == 31) wsum[wid] = inc;
    __syncthreads();
    if (wid == 0) {
        int w = wsum[lane];
        int wi = w;
#pragma unroll
        for (int off = 1; off < 32; off <<= 1) {
            int u = __shfl_up_sync(0xffffffffu, wi, off);
            if (lane >= off) wi += u;
        }
        wsum[lane] = wi - w;                     // exclusive warp offsets
    }
    __syncthreads();
    int exc = (inc - v) + wsum[wid];
    int prun = exc >> 16;
    int nrun = exc & 0xffff;

    for (int n = start; n < end; n++) {
        int c = g_cls[(long)bA * NANCH + n];
        if (c == 1)      { prun++; if (prun > POS_NUM)   c = -1; }
        else if (c == 0) { nrun++; if (nrun > TOTAL_NUM) c = -1; }
        s_cls[n] = (signed char)c;
    }
    __syncthreads();

    const int pn = min(s_pos, POS_NUM);
    const float invp = 1.0f / (float)pn;         // pn==0 -> inf, matches ref
    const long clsB = (long)bA * NANCH;
    const long bwB  = (long)Bn * NANCH * 5 + clsB;

    for (int o = t; o < NANCH; o += 1024) {      // o = a*625 + yx (output order)
        int a = o / (S * S), yx = o - a * (S * S);
        int c = s_cls[yx * A + a];               // LDS stride 5: conflict-free
        out[clsB + o] = (float)c;
        out[bwB + o]  = (c == 1) ? invp : 0.0f;
    }
}

// ---------------- launch ----------------------------------------------------
extern "C" void kernel_launch(void* const* d_in, const int* in_sizes, int n_in,
                              void* d_out, int out_size) {
    (void)n_in; (void)out_size;
    const float4* gt      = (const float4*)d_in[0];   // (B, G, 4)
    const float4* anchors = (const float4*)d_in[1];   // (N, 4)
    const int Bn = in_sizes[0] / (G * 4);             // 128
    float* out = (float*)d_out;

    k_init<<<(BMAX * G + 1023) / 1024, 1024>>>();

    dim3 g1(NBLK, Bn);
    k_iou<<<g1, 128>>>(anchors, gt, out, Bn);
    k_cls<<<g1, 128>>>(out, Bn);
    k_scan<<<Bn, 1024>>>(out, Bn);
}